// round 2
// baseline (speedup 1.0000x reference)
#include <cuda_runtime.h>
#include <stdint.h>

// BitInput: out[i] = (u_i < p[i >> 8]) ? 1.0f : 0.0f
// u_i from jax.random.uniform(key(42)) with threefry_partitionable=True:
//   (b0, b1) = threefry2x32_20(key=(0,42), x0=hi32(i)=0, x1=lo32(i)=i)
//   bits = b0 ^ b1
//   u = bitcast((bits >> 9) | 0x3f800000) - 1.0f

static __device__ __forceinline__ uint32_t rotl32(uint32_t x, int r) {
    return __funnelshift_l(x, x, r);
}

static __device__ __forceinline__ uint32_t bern_bit(uint32_t bits, float p) {
    float u = __uint_as_float((bits >> 9) | 0x3f800000u) - 1.0f;
    return (u < p) ? 0x3f800000u : 0u;  // 1.0f : 0.0f raw bits
}

__global__ void __launch_bounds__(256)
bitinput_kernel(const float* __restrict__ prob, uint4* __restrict__ out)
{
    const uint32_t t  = blockIdx.x * 256u + threadIdx.x;
    const uint32_t i0 = t << 2;                 // 4 consecutive elements
    // 4 consecutive elements share one probability (256 | block of p)
    const float p = __ldg(&prob[i0 >> 8]);

    // key(42): ks0 = 0, ks1 = 42, ks2 = 0 ^ 42 ^ 0x1BD11BDA
    const uint32_t KS1 = 42u;
    const uint32_t KS2 = 0x1BD11BF0u;

    uint32_t r[4];

#pragma unroll
    for (int j = 0; j < 4; ++j) {
        // x0 = hi32(i) + ks0 = 0;  x1 = lo32(i) + ks1
        uint32_t x0 = 0u;
        uint32_t x1 = i0 + (uint32_t)j + KS1;

#define TF_R4(a,b,c,d)                                   \
        x0 += x1; x1 = rotl32(x1,(a)); x1 ^= x0;         \
        x0 += x1; x1 = rotl32(x1,(b)); x1 ^= x0;         \
        x0 += x1; x1 = rotl32(x1,(c)); x1 ^= x0;         \
        x0 += x1; x1 = rotl32(x1,(d)); x1 ^= x0;

        TF_R4(13, 15, 26, 6)
        x0 += KS1;       x1 += KS2 + 1u;
        TF_R4(17, 29, 16, 24)
        x0 += KS2;       x1 += 2u;            // ks0 = 0
        TF_R4(13, 15, 26, 6)
        /* x0 += 0 */    x1 += KS1 + 3u;
        TF_R4(17, 29, 16, 24)
        x0 += KS1;       x1 += KS2 + 4u;
        TF_R4(13, 15, 26, 6)
        x0 += KS2;       x1 += 5u;            // ks0 = 0
#undef TF_R4

        r[j] = x0 ^ x1;   // partitionable mode: bits = out0 ^ out1
    }

    uint4 v;
    v.x = bern_bit(r[0], p);
    v.y = bern_bit(r[1], p);
    v.z = bern_bit(r[2], p);
    v.w = bern_bit(r[3], p);

    __stcs(&out[t], v);
}

extern "C" void kernel_launch(void* const* d_in, const int* in_sizes, int n_in,
                              void* d_out, int out_size)
{
    const float* prob = (const float*)d_in[0];
    const uint32_t n      = (uint32_t)out_size;   // 134,217,728
    const uint32_t nthr   = n >> 2;               // 4 outputs per thread
    const uint32_t blocks = nthr / 256u;

    bitinput_kernel<<<blocks, 256>>>(prob, (uint4*)d_out);
}